// round 9
// baseline (speedup 1.0000x reference)
#include <cuda_runtime.h>
#include <cuda_fp16.h>
#include <math.h>

#define D 128
#define NMAX 50000
#define EMAX 800000
#define BM 64
#define NCNT 512   // grid-stride cnt blocks fused into the GEMM launch

// Scratch (device globals — zero-init at load; k_reset keeps cnt/degex zero)
__device__ uint2 g_xwh[(size_t)NMAX * 32];  // x @ W packed 4x fp16 per lane
__device__ float g_p1[NMAX];                // x . w_pred[:128]
__device__ float g_p2[NMAX];                // x . w_pred[128:]
__device__ float g_degex[NMAX];             // weighted in-degree EXCESS (deg-1)
__device__ int   g_cnt[NMAX];               // in-degree count (by tgt)
__device__ int   g_rowstart[NMAX + 1];      // CSR row offsets (by tgt)
__device__ int   g_cursor[NMAX];            // fill cursors
__device__ int2  g_pack[EMAX];              // (src, ew bits) grouped by tgt

// ---------------------------------------------------------------------------
// K1 (fused): blocks [0, ngemm): FFMA2 GEMM -> fp16 xwh, PLUS p1/p2 from the
//             resident X smem tile (warp-per-8-rows dot + shuffle reduce).
//             blocks [ngemm, ...): grid-stride in-degree counts by target.
// ---------------------------------------------------------------------------
__global__ void k_gemmcnt(const float* __restrict__ x,
                          const float* __restrict__ W,
                          const float* __restrict__ wp,
                          const int* __restrict__ tgt,
                          int n, int e, int ngemm) {
    if ((int)blockIdx.x >= ngemm) {
        int nblk = gridDim.x - ngemm;
        for (int i = (blockIdx.x - ngemm) * 256 + threadIdx.x; i < e;
             i += nblk * 256)
            atomicAdd(&g_cnt[tgt[i]], 1);
        return;
    }

    extern __shared__ float sh[];
    float* Ws = sh;            // [k][j]  128*128
    float* Xs = sh + D * D;    // [r][k]  BM*128
    int tid = threadIdx.x;
    int warp = tid >> 5;
    int lane = tid & 31;
    int row0 = blockIdx.x * BM;

    for (int i = tid; i < D * D / 4; i += 256)
        ((float4*)Ws)[i] = ((const float4*)W)[i];
    for (int i = tid; i < BM * D / 4; i += 256) {
        int r = i >> 5;
        int gr = row0 + r;
        float4 v = make_float4(0.f, 0.f, 0.f, 0.f);
        if (gr < n) v = ((const float4*)x)[(size_t)gr * 32 + (i & 31)];
        ((float4*)Xs)[i] = v;
    }
    __syncthreads();

    int tcol = lane;   // cols tcol*4 .. +3
    int trow = warp;   // rows trow*8 .. +7

    unsigned long long acc[8][2];
#pragma unroll
    for (int i = 0; i < 8; i++) {
        acc[i][0] = 0ull;
        acc[i][1] = 0ull;
    }

#pragma unroll 4
    for (int k = 0; k < D; k++) {
        float4 bv = *((const float4*)&Ws[k * D + tcol * 4]);
        unsigned long long b01, b23;
        asm("mov.b64 %0, {%1, %2};" : "=l"(b01) : "f"(bv.x), "f"(bv.y));
        asm("mov.b64 %0, {%1, %2};" : "=l"(b23) : "f"(bv.z), "f"(bv.w));
#pragma unroll
        for (int i = 0; i < 8; i++) {
            float a = Xs[(trow * 8 + i) * D + k];
            unsigned long long aa;
            asm("mov.b64 %0, {%1, %1};" : "=l"(aa) : "f"(a));
            asm("fma.rn.f32x2 %0, %1, %2, %0;" : "+l"(acc[i][0])
                : "l"(aa), "l"(b01));
            asm("fma.rn.f32x2 %0, %1, %2, %0;" : "+l"(acc[i][1])
                : "l"(aa), "l"(b23));
        }
    }

#pragma unroll
    for (int i = 0; i < 8; i++) {
        int gr = row0 + trow * 8 + i;
        if (gr < n) {
            float c0, c1, c2, c3;
            asm("mov.b64 {%0, %1}, %2;" : "=f"(c0), "=f"(c1) : "l"(acc[i][0]));
            asm("mov.b64 {%0, %1}, %2;" : "=f"(c2), "=f"(c3) : "l"(acc[i][1]));
            __half2 h01 = __floats2half2_rn(c0, c1);
            __half2 h23 = __floats2half2_rn(c2, c3);
            uint2 pk;
            pk.x = *(unsigned*)&h01;
            pk.y = *(unsigned*)&h23;
            g_xwh[(size_t)gr * 32 + tcol] = pk;
        }
    }

    // p-phase: rows are still in Xs; warp w handles rows w*8 .. w*8+7.
    float4 w1 = ((const float4*)wp)[lane];
    float4 w2 = ((const float4*)(wp + D))[lane];
#pragma unroll
    for (int r = 0; r < 8; r++) {
        int row = warp * 8 + r;
        float4 xv = *(const float4*)&Xs[row * D + lane * 4];
        float s1 = xv.x * w1.x + xv.y * w1.y + xv.z * w1.z + xv.w * w1.w;
        float s2 = xv.x * w2.x + xv.y * w2.y + xv.z * w2.z + xv.w * w2.w;
#pragma unroll
        for (int o = 16; o > 0; o >>= 1) {
            s1 += __shfl_xor_sync(0xffffffffu, s1, o);
            s2 += __shfl_xor_sync(0xffffffffu, s2, o);
        }
        int gr = row0 + row;
        if (lane == 0 && gr < n) {
            g_p1[gr] = s1;
            g_p2[gr] = s2;
        }
    }
}

// ---------------------------------------------------------------------------
// K2: single-block 1024-thread exclusive scan of g_cnt with next-tile
// prefetch (49 coalesced tiles, latency-hidden) -> rowstart, cursor.
// ---------------------------------------------------------------------------
__global__ void k_scan(int n, int e) {
    __shared__ int wsum[32];
    int tid = threadIdx.x;
    int lane = tid & 31, wid = tid >> 5;
    int carry = 0;
    int v = (tid < n) ? g_cnt[tid] : 0;  // tile 0 prefetch

    for (int base = 0; base < n; base += 1024) {
        int i = base + tid;
        int inext = i + 1024;
        int vnext = (inext < n) ? g_cnt[inext] : 0;  // prefetch next tile

        // inclusive warp scan
        int xinc = v;
#pragma unroll
        for (int o = 1; o < 32; o <<= 1) {
            int y = __shfl_up_sync(0xffffffffu, xinc, o);
            if (lane >= o) xinc += y;
        }
        if (lane == 31) wsum[wid] = xinc;
        __syncthreads();
        if (wid == 0) {
            int w = wsum[lane];
#pragma unroll
            for (int o = 1; o < 32; o <<= 1) {
                int y = __shfl_up_sync(0xffffffffu, w, o);
                if (lane >= o) w += y;
            }
            wsum[lane] = w;  // inclusive scan of warp sums
        }
        __syncthreads();
        int woff = (wid > 0) ? wsum[wid - 1] : 0;
        int excl = carry + woff + xinc - v;
        if (i < n) {
            g_rowstart[i] = excl;
            g_cursor[i] = excl;
        }
        carry += wsum[31];
        __syncthreads();  // wsum reused next tile
        v = vnext;
    }
    if (tid == 0) g_rowstart[n] = e;
}

// ---------------------------------------------------------------------------
// K3: edge weights (sigmoid) + weighted in-degree excess + CSR fill by tgt.
// ---------------------------------------------------------------------------
__global__ void k_edgefill(const int* __restrict__ src,
                           const int* __restrict__ tgt,
                           const float* __restrict__ bp, int e) {
    int i = blockIdx.x * blockDim.x + threadIdx.x;
    if (i >= e) return;
    int s = src[i], t = tgt[i];
    float z = g_p1[s] + g_p2[t] + bp[0];
    float w = __fdividef(1.0f, 1.0f + __expf(-z));
    atomicAdd(&g_degex[t], w);
    int pos = atomicAdd(&g_cursor[t], 1);
    g_pack[pos] = make_int2(s, __float_as_int(w));
}

// ---------------------------------------------------------------------------
// K4: atomic-free aggregation, warp per TARGET node. Lane-parallel edge
// metadata; 8-way unrolled independent fp16 row gathers (256B/edge).
// Self term also fp16 (xwh). Bias folded; output row written exactly once.
// ---------------------------------------------------------------------------
__global__ void k_aggregate(const float* __restrict__ b,
                            float* __restrict__ out, int n) {
    int t = (blockIdx.x * blockDim.x + threadIdx.x) >> 5;
    int lane = threadIdx.x & 31;
    if (t >= n) return;
    float dt = rsqrtf(1.0f + g_degex[t]);
    uint2 sv = g_xwh[(size_t)t * 32 + lane];
    float2 sa = __half22float2(*(__half2*)&sv.x);
    float2 sb = __half22float2(*(__half2*)&sv.y);
    float sc = dt * dt;
    float4 acc = make_float4(sc * sa.x, sc * sa.y, sc * sb.x, sc * sb.y);

    int p0 = g_rowstart[t];
    int cnt = g_rowstart[t + 1] - p0;

    for (int base = 0; base < cnt; base += 32) {
        int idx = base + lane;
        int s = 0;
        float c = 0.f;
        if (idx < cnt) {
            int2 pk = g_pack[p0 + idx];
            s = pk.x;
            c = __int_as_float(pk.y) * rsqrtf(1.0f + g_degex[s]) * dt;
        }
        int m = min(32, cnt - base);
        int j = 0;
        for (; j + 8 <= m; j += 8) {
            int ss[8];
            float cc[8];
#pragma unroll
            for (int q = 0; q < 8; q++) {
                ss[q] = __shfl_sync(0xffffffffu, s, j + q);
                cc[q] = __shfl_sync(0xffffffffu, c, j + q);
            }
            uint2 vv[8];
#pragma unroll
            for (int q = 0; q < 8; q++)
                vv[q] = g_xwh[(size_t)ss[q] * 32 + lane];
#pragma unroll
            for (int q = 0; q < 8; q++) {
                float2 a = __half22float2(*(__half2*)&vv[q].x);
                float2 d = __half22float2(*(__half2*)&vv[q].y);
                acc.x += cc[q] * a.x;
                acc.y += cc[q] * a.y;
                acc.z += cc[q] * d.x;
                acc.w += cc[q] * d.y;
            }
        }
        for (; j < m; j++) {
            int sj = __shfl_sync(0xffffffffu, s, j);
            float cj = __shfl_sync(0xffffffffu, c, j);
            uint2 v = g_xwh[(size_t)sj * 32 + lane];
            float2 a = __half22float2(*(__half2*)&v.x);
            float2 d = __half22float2(*(__half2*)&v.y);
            acc.x += cj * a.x;
            acc.y += cj * a.y;
            acc.z += cj * d.x;
            acc.w += cj * d.y;
        }
    }

    float4 bv = ((const float4*)b)[lane];
    ((float4*)out)[(size_t)t * 32 + lane] =
        make_float4(acc.x + bv.x, acc.y + bv.y, acc.z + bv.z, acc.w + bv.w);
}

// ---------------------------------------------------------------------------
// K5: restore g_cnt/g_degex to zero so every invocation starts identically.
// ---------------------------------------------------------------------------
__global__ void k_reset(int n) {
    int i = blockIdx.x * blockDim.x + threadIdx.x;
    if (i >= n) return;
    g_cnt[i] = 0;
    g_degex[i] = 0.0f;
}

// ---------------------------------------------------------------------------
extern "C" void kernel_launch(void* const* d_in, const int* in_sizes, int n_in,
                              void* d_out, int out_size) {
    const float* x  = (const float*)d_in[0];
    const int*   ei = (const int*)d_in[1];
    const float* W  = (const float*)d_in[2];
    const float* b  = (const float*)d_in[3];
    const float* wp = (const float*)d_in[4];
    const float* bp = (const float*)d_in[5];
    float* out = (float*)d_out;

    int n = in_sizes[0] / D;
    int e = in_sizes[1] / 2;
    const int* src = ei;
    const int* tgt = ei + e;
    int ngemm = (n + BM - 1) / BM;

    int smem = (D * D + BM * D) * (int)sizeof(float);  // 96 KB
    cudaFuncSetAttribute(k_gemmcnt, cudaFuncAttributeMaxDynamicSharedMemorySize,
                         smem);

    k_gemmcnt<<<ngemm + NCNT, 256, smem>>>(x, W, wp, tgt, n, e, ngemm);
    k_scan<<<1, 1024>>>(n, e);
    k_edgefill<<<(e + 255) / 256, 256>>>(src, tgt, bp, e);
    k_aggregate<<<(n * 32 + 255) / 256, 256>>>(b, out, n);
    k_reset<<<(n + 255) / 256, 256>>>(n);
}